// round 2
// baseline (speedup 1.0000x reference)
#include <cuda_runtime.h>
#include <math.h>

// Problem constants (fixed by the reference).
#define NN 65536   // nodes
#define KK 8       // children
#define HH 128     // hidden size
#define TT 4       // types
#define NT 8       // nodes per block in main kernel
#define MAIN_BLOCKS (NN / NT + TT)   // 8196: covers per-type ceil rounding

// ---------------- f32x2 helpers (sm_103a packed fp32 pipe) ----------------
__device__ __forceinline__ unsigned long long dup2(float x) {
    unsigned long long r;
    asm("mov.b64 %0, {%1, %1};" : "=l"(r) : "f"(x));
    return r;
}
__device__ __forceinline__ unsigned long long ffma2(unsigned long long a,
                                                    unsigned long long b,
                                                    unsigned long long c) {
    unsigned long long d;
    asm("fma.rn.f32x2 %0, %1, %2, %3;" : "=l"(d) : "l"(a), "l"(b), "l"(c));
    return d;
}
__device__ __forceinline__ float2 unpk(unsigned long long v) {
    float2 f;
    asm("mov.b64 {%0, %1}, %2;" : "=f"(f.x), "=f"(f.y) : "l"(v));
    return f;
}

// ---------------- device scratch (no allocations allowed) ----------------
__device__ int g_cnt[TT];
__device__ int g_base[TT + 1];
__device__ int g_cursor[TT];
__device__ int g_sorted[NN];

// ---------------- partition pipeline ----------------
__global__ void k_zero() {
    if (threadIdx.x < TT) g_cnt[threadIdx.x] = 0;
}

__global__ void k_hist(const int* __restrict__ type_id) {
    __shared__ int sc[TT];
    if (threadIdx.x < TT) sc[threadIdx.x] = 0;
    __syncthreads();
    int n = blockIdx.x * blockDim.x + threadIdx.x;
    atomicAdd(&sc[type_id[n]], 1);
    __syncthreads();
    if (threadIdx.x < TT) atomicAdd(&g_cnt[threadIdx.x], sc[threadIdx.x]);
}

__global__ void k_scan() {
    g_base[0] = 0;
    for (int t = 0; t < TT; t++) {
        g_base[t + 1] = g_base[t] + g_cnt[t];
        g_cursor[t] = g_base[t];
    }
}

// Block-aggregated scatter: 4 global atomics per 256-thread block.
__global__ void k_scatter(const int* __restrict__ type_id) {
    __shared__ int w_off[8][TT];
    __shared__ int blk_base[TT];
    int n = blockIdx.x * 256 + threadIdx.x;
    int t = type_id[n];
    int w = threadIdx.x >> 5, lane = threadIdx.x & 31;
    int rank = 0;
#pragma unroll
    for (int tt = 0; tt < TT; tt++) {
        unsigned b = __ballot_sync(0xffffffffu, t == tt);
        if (lane == 0) w_off[w][tt] = __popc(b);
        if (t == tt) rank = __popc(b & ((1u << lane) - 1));
    }
    __syncthreads();
    if (threadIdx.x < TT) {
        int tt = threadIdx.x;
        int s = 0;
#pragma unroll
        for (int ww = 0; ww < 8; ww++) { int v = w_off[ww][tt]; w_off[ww][tt] = s; s += v; }
        blk_base[tt] = atomicAdd(&g_cursor[tt], s);
    }
    __syncthreads();
    g_sorted[blk_base[t] + w_off[w][t] + rank] = n;
}

// ---------------- main kernel ----------------
// Block = NT same-type nodes. 128 threads; thread o owns output column o.
// f32x2 packing: forget gate packs child pairs, IOU packs node pairs.
__global__ __launch_bounds__(128) void k_main(
    const float* __restrict__ h, const float* __restrict__ c,
    const float* __restrict__ f_input,
    const float* __restrict__ U_iou, const float* __restrict__ b_iou,
    const float* __restrict__ U_f, const float* __restrict__ b_f,
    float* __restrict__ out)
{
    __shared__ __align__(16) float sh_ht[NT][HH][KK];   // h transposed: [n][j][k], 32 KB
    __shared__ __align__(16) float sh_hst[HH][NT];      // child-sum transposed: [j][n], 4 KB
    __shared__ int sh_node[NT];

    // ---- find my type + row chunk from g_base (no empty-block waste) ----
    int b = blockIdx.x;
    int t = 0, rowstart = -1;
    {
        int cb = 0;
#pragma unroll
        for (int tt = 0; tt < TT; tt++) {
            int lo = g_base[tt], hi = g_base[tt + 1];
            int ch = (hi - lo + NT - 1) / NT;
            if (b >= cb && b < cb + ch) { t = tt; rowstart = lo + (b - cb) * NT; }
            cb += ch;
        }
    }
    if (rowstart < 0) return;
    const int cnt = min(NT, g_base[t + 1] - rowstart);
    const int o = threadIdx.x;

    if (o < NT) sh_node[o] = g_sorted[rowstart + ((o < cnt) ? o : 0)];
    __syncthreads();

    // ---- gather h rows + transpose into [n][j][k] ----
    // lane mapping k-minor: coalesced-enough reads, 4-way-conflict one-time writes
#pragma unroll
    for (int it = 0; it < 16; it++) {
        int flat = o + 128 * it;          // 2048 float4 tasks
        int k = flat & 7;
        int j4 = (flat >> 3) & 31;
        int n = flat >> 8;
        const float4 hv = *reinterpret_cast<const float4*>(
            &h[(sh_node[n] * KK + k) * HH + j4 * 4]);
        sh_ht[n][4 * j4 + 0][k] = hv.x;
        sh_ht[n][4 * j4 + 1][k] = hv.y;
        sh_ht[n][4 * j4 + 2][k] = hv.z;
        sh_ht[n][4 * j4 + 3][k] = hv.w;
    }
    __syncthreads();

    // ---- child-sum, transposed [j][n] ----
#pragma unroll
    for (int it = 0; it < 8; it++) {
        int flat = o + 128 * it;          // 1024 tasks
        int j = flat & 127, n = flat >> 7;
        float4 a = *reinterpret_cast<const float4*>(&sh_ht[n][j][0]);
        float4 bb = *reinterpret_cast<const float4*>(&sh_ht[n][j][4]);
        sh_hst[j][n] = ((a.x + a.y) + (a.z + a.w)) + ((bb.x + bb.y) + (bb.z + bb.w));
    }
    __syncthreads();

    // ---- IOU: node-pair packed f32x2 ----
    const float* Ut = U_iou + t * (HH * 3 * HH);
    unsigned long long a2[3][NT / 2];
#pragma unroll
    for (int s = 0; s < 3; s++)
#pragma unroll
        for (int p = 0; p < NT / 2; p++) a2[s][p] = 0ull;

#pragma unroll 2
    for (int j = 0; j < HH; j++) {
        unsigned long long u0 = dup2(Ut[j * 384 + o]);
        unsigned long long u1 = dup2(Ut[j * 384 + 128 + o]);
        unsigned long long u2 = dup2(Ut[j * 384 + 256 + o]);
        const ulonglong2* sp = reinterpret_cast<const ulonglong2*>(&sh_hst[j][0]);
        ulonglong2 sA = sp[0];   // node pairs (0,1),(2,3)
        ulonglong2 sB = sp[1];   // node pairs (4,5),(6,7)
        a2[0][0] = ffma2(sA.x, u0, a2[0][0]);
        a2[0][1] = ffma2(sA.y, u0, a2[0][1]);
        a2[0][2] = ffma2(sB.x, u0, a2[0][2]);
        a2[0][3] = ffma2(sB.y, u0, a2[0][3]);
        a2[1][0] = ffma2(sA.x, u1, a2[1][0]);
        a2[1][1] = ffma2(sA.y, u1, a2[1][1]);
        a2[1][2] = ffma2(sB.x, u1, a2[1][2]);
        a2[1][3] = ffma2(sB.y, u1, a2[1][3]);
        a2[2][0] = ffma2(sA.x, u2, a2[2][0]);
        a2[2][1] = ffma2(sA.y, u2, a2[2][1]);
        a2[2][2] = ffma2(sB.x, u2, a2[2][2]);
        a2[2][3] = ffma2(sB.y, u2, a2[2][3]);
    }
    {
        float bi0 = b_iou[t * 384 + o];
        float bi1 = b_iou[t * 384 + 128 + o];
        float bi2 = b_iou[t * 384 + 256 + o];
#pragma unroll
        for (int p = 0; p < NT / 2; p++) {
            float2 v0 = unpk(a2[0][p]);
            float2 v1 = unpk(a2[1][p]);
            float2 v2 = unpk(a2[2][p]);
            int n0 = 2 * p, n1 = 2 * p + 1;
            if (n0 < cnt) {
                int nd = sh_node[n0];
                out[nd * 512 + o]       = v0.x + bi0;
                out[nd * 512 + 128 + o] = v1.x + bi1;
                out[nd * 512 + 256 + o] = v2.x + bi2;
            }
            if (n1 < cnt) {
                int nd = sh_node[n1];
                out[nd * 512 + o]       = v0.y + bi0;
                out[nd * 512 + 128 + o] = v1.y + bi1;
                out[nd * 512 + 256 + o] = v2.y + bi2;
            }
        }
    }

    // ---- Forget gates: child-pair packed f32x2 ----
    const float* Uf = U_f + t * (HH * HH);
    unsigned long long fa[NT][KK / 2];   // 8 nodes x 4 child-pairs = 64 regs
#pragma unroll
    for (int n = 0; n < NT; n++)
#pragma unroll
        for (int p = 0; p < KK / 2; p++) fa[n][p] = 0ull;

#pragma unroll 2
    for (int j = 0; j < HH; j++) {
        unsigned long long up = dup2(Uf[j * 128 + o]);
#pragma unroll
        for (int n = 0; n < NT; n++) {
            const ulonglong2* hp = reinterpret_cast<const ulonglong2*>(&sh_ht[n][j][0]);
            ulonglong2 hA = hp[0];   // child pairs (0,1),(2,3)
            ulonglong2 hB = hp[1];   // child pairs (4,5),(6,7)
            fa[n][0] = ffma2(hA.x, up, fa[n][0]);
            fa[n][1] = ffma2(hA.y, up, fa[n][1]);
            fa[n][2] = ffma2(hB.x, up, fa[n][2]);
            fa[n][3] = ffma2(hB.y, up, fa[n][3]);
        }
    }

    // ---- epilogue: sigmoid + weighted cell sum ----
    {
        const float bf = b_f[t * HH + o];
#pragma unroll
        for (int n = 0; n < NT; n++) {
            if (n < cnt) {
                int nd = sh_node[n];
                float fi = f_input[nd * HH + o] + bf;
                float ca = 0.f;
#pragma unroll
                for (int p = 0; p < KK / 2; p++) {
                    float2 fv = unpk(fa[n][p]);
                    float c0 = c[nd * (KK * HH) + (2 * p) * HH + o];
                    float c1 = c[nd * (KK * HH) + (2 * p + 1) * HH + o];
                    float s0 = 1.f / (1.f + __expf(-(fv.x + fi)));
                    float s1 = 1.f / (1.f + __expf(-(fv.y + fi)));
                    ca = fmaf(s0, c0, ca);
                    ca = fmaf(s1, c1, ca);
                }
                out[nd * 512 + 384 + o] = ca;
            }
        }
    }
}

// ---------------- launch ----------------
extern "C" void kernel_launch(void* const* d_in, const int* in_sizes, int n_in,
                              void* d_out, int out_size) {
    const float* h       = (const float*)d_in[0];
    const float* c       = (const float*)d_in[1];
    const float* f_input = (const float*)d_in[2];
    const int*   type_id = (const int*)d_in[3];
    const float* U_iou   = (const float*)d_in[4];
    const float* b_iou   = (const float*)d_in[5];
    const float* U_f     = (const float*)d_in[6];
    const float* b_f     = (const float*)d_in[7];
    float* out = (float*)d_out;

    k_zero<<<1, 32>>>();
    k_hist<<<NN / 256, 256>>>(type_id);
    k_scan<<<1, 1>>>();
    k_scatter<<<NN / 256, 256>>>(type_id);
    k_main<<<MAIN_BLOCKS, 128>>>(h, c, f_input, U_iou, b_iou, U_f, b_f, out);
}

// round 4
// speedup vs baseline: 1.3118x; 1.3118x over previous
#include <cuda_runtime.h>
#include <cuda_bf16.h>
#include <math.h>
#include <cstdint>

// Problem constants.
#define NN 65536
#define KK 8
#define HH 128
#define TT 4

#define NTF 16                      // nodes per CTA, forget kernel (M=128 rows)
#define GRID_F (NN / NTF + TT)
#define NTI 128                     // nodes per CTA, iou kernel
#define GRID_I (NN / NTI + TT)

#define SW128(x) ((x) ^ (((x) >> 3) & 0x70))

// ---- forget kernel smem map (dynamic) ----
#define F_AHI 1024
#define F_ALO (F_AHI + 16384)
#define F_BHI (F_ALO + 16384)
#define F_BLO (F_BHI + 16384)
#define F_FI  (F_BLO + 16384)          // 16*128 f32 = 8192
#define F_SMEM (F_FI + 8192)           // 74752

// ---- iou kernel smem map ----
#define I_BIAS 512
#define I_AHI 1024                     // [2 halves][128][64] bf16 = 32768
#define I_ALO (I_AHI + 32768)
#define I_BHI (I_ALO + 32768)
#define I_BLO (I_BHI + 16384)
#define I_SMEM (I_BLO + 16384)         // 99328

// ---------------- device scratch ----------------
__device__ int g_cnt[TT];
__device__ int g_base[TT + 1];
__device__ int g_cursor[TT];
__device__ int g_sorted[NN];
__device__ float g_hsum[NN * HH];

// ---------------- helpers ----------------
__device__ __forceinline__ uint32_t smem_u32(const void* p) {
    uint32_t a;
    asm("{ .reg .u64 t; cvta.to.shared.u64 t, %1; cvt.u32.u64 %0, t; }" : "=r"(a) : "l"(p));
    return a;
}
__device__ __forceinline__ uint32_t pack_bf(float a, float b) {
    __nv_bfloat162 t = __floats2bfloat162_rn(a, b);
    return *reinterpret_cast<uint32_t*>(&t);
}
__device__ __forceinline__ void split_bf(float v0, float v1, uint32_t& hi, uint32_t& lo) {
    __nv_bfloat16 h0 = __float2bfloat16_rn(v0);
    __nv_bfloat16 h1 = __float2bfloat16_rn(v1);
    hi = ((uint32_t)*reinterpret_cast<uint16_t*>(&h1) << 16) | *reinterpret_cast<uint16_t*>(&h0);
    lo = pack_bf(v0 - __bfloat162float(h0), v1 - __bfloat162float(h1));
}
__device__ __forceinline__ void ldsm_x4(uint32_t* r, uint32_t addr) {
    asm volatile("ldmatrix.sync.aligned.m8n8.x4.shared.b16 {%0,%1,%2,%3}, [%4];"
        : "=r"(r[0]), "=r"(r[1]), "=r"(r[2]), "=r"(r[3]) : "r"(addr));
}
__device__ __forceinline__ void mma16816(float* d, const uint32_t* a, const uint32_t* b) {
    asm volatile("mma.sync.aligned.m16n8k16.row.col.f32.bf16.bf16.f32 "
        "{%0,%1,%2,%3}, {%4,%5,%6,%7}, {%8,%9}, {%0,%1,%2,%3};"
        : "+f"(d[0]), "+f"(d[1]), "+f"(d[2]), "+f"(d[3])
        : "r"(a[0]), "r"(a[1]), "r"(a[2]), "r"(a[3]), "r"(b[0]), "r"(b[1]));
}
__device__ __forceinline__ float sigm(float x) { return 1.f / (1.f + __expf(-x)); }

// Find (type, rowstart, cnt) for this block given nodes-per-CTA NT.
__device__ __forceinline__ bool find_chunk(int b, int NT, int& t, int& rowstart, int& cnt) {
    int cb = 0;
#pragma unroll
    for (int tt = 0; tt < TT; tt++) {
        int lo = g_base[tt], hi = g_base[tt + 1];
        int ch = (hi - lo + NT - 1) / NT;
        if (b >= cb && b < cb + ch) {
            t = tt;
            rowstart = lo + (b - cb) * NT;
            cnt = min(NT, hi - rowstart);
            return true;
        }
        cb += ch;
    }
    return false;
}

// ---------------- partition pipeline ----------------
__global__ void k_zero() {
    if (threadIdx.x < TT) g_cnt[threadIdx.x] = 0;
}
__global__ void k_hist(const int* __restrict__ type_id) {
    __shared__ int sc[TT];
    if (threadIdx.x < TT) sc[threadIdx.x] = 0;
    __syncthreads();
    int n = blockIdx.x * blockDim.x + threadIdx.x;
    atomicAdd(&sc[type_id[n]], 1);
    __syncthreads();
    if (threadIdx.x < TT) atomicAdd(&g_cnt[threadIdx.x], sc[threadIdx.x]);
}
__global__ void k_scan() {
    g_base[0] = 0;
    for (int t = 0; t < TT; t++) {
        g_base[t + 1] = g_base[t] + g_cnt[t];
        g_cursor[t] = g_base[t];
    }
}
__global__ void k_scatter(const int* __restrict__ type_id) {
    __shared__ int w_off[8][TT];
    __shared__ int blk_base[TT];
    int n = blockIdx.x * 256 + threadIdx.x;
    int t = type_id[n];
    int w = threadIdx.x >> 5, lane = threadIdx.x & 31;
    int rank = 0;
#pragma unroll
    for (int tt = 0; tt < TT; tt++) {
        unsigned bm = __ballot_sync(0xffffffffu, t == tt);
        if (lane == 0) w_off[w][tt] = __popc(bm);
        if (t == tt) rank = __popc(bm & ((1u << lane) - 1));
    }
    __syncthreads();
    if (threadIdx.x < TT) {
        int tt = threadIdx.x, s = 0;
#pragma unroll
        for (int ww = 0; ww < 8; ww++) { int v = w_off[ww][tt]; w_off[ww][tt] = s; s += v; }
        blk_base[tt] = atomicAdd(&g_cursor[tt], s);
    }
    __syncthreads();
    g_sorted[blk_base[t] + w_off[w][t] + rank] = n;
}

// ---------------- forget-gate GEMM (bf16 mma.sync, 2-term split) ----------------
// CTA = 16 same-type nodes -> M=128 rows (node*8+child), N=128, K=128.
// Side product: g_hsum. Fused epilogue: sigmoid(x + f_input + b_f) * c, sum children.
__global__ __launch_bounds__(256) void k_forget(
    const float* __restrict__ h, const float* __restrict__ c,
    const float* __restrict__ f_input, const float* __restrict__ U_f,
    const float* __restrict__ b_f, float* __restrict__ out)
{
    extern __shared__ __align__(1024) char smem[];
    const uint32_t sb = smem_u32(smem);
    const int tid = threadIdx.x, wid = tid >> 5, lane = tid & 31;

    int t, rowstart, cnt;
    if (!find_chunk(blockIdx.x, NTF, t, rowstart, cnt)) return;

    int* sh_node = (int*)smem;
    float* fi = (float*)(smem + F_FI);
    if (tid < NTF) sh_node[tid] = g_sorted[rowstart + min(tid, cnt - 1)];
    __syncthreads();

    // fi stage: f_input[node] + b_f (16 x 128)
#pragma unroll
    for (int i = 0; i < 8; i++) {
        int idx = tid + 256 * i;
        int n = idx >> 7, col = idx & 127;
        fi[idx] = f_input[(size_t)sh_node[n] * HH + col] + b_f[t * HH + col];
    }

    float acc[16][4];
#pragma unroll
    for (int i = 0; i < 16; i++)
#pragma unroll
        for (int j = 0; j < 4; j++) acc[i][j] = 0.f;

    const int mbase = wid * 16;
    const uint32_t offA0 = (uint32_t)((mbase + (lane & 15)) * 128 + ((lane >> 4) << 4));
    const uint32_t swA = (offA0 >> 3) & 0x70;
    const uint32_t offB0 = (uint32_t)(((lane & 7) + ((lane >> 4) << 3)) * 128 + ((lane & 8) * 2));
    const uint32_t swB = (offB0 >> 3) & 0x70;

    for (int kc = 0; kc < 2; kc++) {
        // ---- A loader + h_sum: tasks (n=16, jl2=32) ----
#pragma unroll
        for (int i = 0; i < 2; i++) {
            int task = tid + 256 * i;
            int jl2 = task & 31, n = task >> 5;
            int nd = sh_node[n];
            const float* hp0 = h + (size_t)nd * KK * HH + kc * 64 + 2 * jl2;
            float s0 = 0.f, s1 = 0.f;
#pragma unroll
            for (int k = 0; k < KK; k++) {
                float2 v = *(const float2*)(hp0 + k * HH);
                s0 += v.x; s1 += v.y;
                uint32_t hi, lo;
                split_bf(v.x, v.y, hi, lo);
                uint32_t off = SW128((uint32_t)((n * KK + k) * 128 + jl2 * 4));
                *(uint32_t*)(smem + F_AHI + off) = hi;
                *(uint32_t*)(smem + F_ALO + off) = lo;
            }
            *(float2*)&g_hsum[(size_t)nd * HH + kc * 64 + 2 * jl2] = make_float2(s0, s1);
        }
        // ---- B loader: Bt[col][jl] = U_f[t][kc*64+jl][col] ----
#pragma unroll 4
        for (int i = 0; i < 16; i++) {
            int jl2 = i * 2 + (tid >> 7);
            int col = tid & 127;
            const float* Up = U_f + (size_t)t * HH * HH + (kc * 64 + 2 * jl2) * HH + col;
            float v0 = Up[0];
            float v1 = Up[HH];
            uint32_t hi, lo;
            split_bf(v0, v1, hi, lo);
            uint32_t off = SW128((uint32_t)(col * 128 + jl2 * 4));
            *(uint32_t*)(smem + F_BHI + off) = hi;
            *(uint32_t*)(smem + F_BLO + off) = lo;
        }
        __syncthreads();
        // ---- mma: 3 products (hi.hi, hi.lo, lo.hi) ----
#pragma unroll
        for (int pass = 0; pass < 3; pass++) {
            uint32_t Ab = sb + (pass == 2 ? F_ALO : F_AHI);
            uint32_t Bb = sb + (pass == 1 ? F_BLO : F_BHI);
#pragma unroll
            for (int ks = 0; ks < 4; ks++) {
                uint32_t af[4];
                ldsm_x4(af, Ab + ((offA0 + ks * 32) ^ swA));
#pragma unroll
                for (int nt2 = 0; nt2 < 8; nt2++) {
                    uint32_t bfr[4];
                    ldsm_x4(bfr, Bb + nt2 * 2048 + ((offB0 + ks * 32) ^ swB));
                    mma16816(acc[2 * nt2], af, bfr);
                    mma16816(acc[2 * nt2 + 1], af, bfr + 2);
                }
            }
        }
        __syncthreads();
    }

    // ---- epilogue: sigmoid * c, reduce over 8 children, store ----
    const int node0 = wid * 2, node1 = node0 + 1;
    const int child = lane >> 2, q = lane & 3;
    const int nd0 = sh_node[node0], nd1 = sh_node[node1];
    const float* c0p = c + ((size_t)nd0 * KK + child) * HH;
    const float* c1p = c + ((size_t)nd1 * KK + child) * HH;
#pragma unroll
    for (int nt = 0; nt < 16; nt++) {
        int col = nt * 8 + 2 * q;
        float2 f0 = *(float2*)&fi[node0 * 128 + col];
        float2 f1 = *(float2*)&fi[node1 * 128 + col];
        float2 cv0 = *(const float2*)(c0p + col);
        float2 cv1 = *(const float2*)(c1p + col);
        float v00 = sigm(acc[nt][0] + f0.x) * cv0.x;
        float v01 = sigm(acc[nt][1] + f0.y) * cv0.y;
        float v10 = sigm(acc[nt][2] + f1.x) * cv1.x;
        float v11 = sigm(acc[nt][3] + f1.y) * cv1.y;
#pragma unroll
        for (int d = 4; d < 32; d <<= 1) {
            v00 += __shfl_xor_sync(0xffffffffu, v00, d);
            v01 += __shfl_xor_sync(0xffffffffu, v01, d);
            v10 += __shfl_xor_sync(0xffffffffu, v10, d);
            v11 += __shfl_xor_sync(0xffffffffu, v11, d);
        }
        if (lane < 4 && node0 < cnt)
            *(float2*)&out[(size_t)nd0 * 512 + 384 + nt * 8 + 2 * lane] = make_float2(v00, v01);
        if (lane >= 4 && lane < 8 && node1 < cnt)
            *(float2*)&out[(size_t)nd1 * 512 + 384 + nt * 8 + 2 * (lane - 4)] = make_float2(v10, v11);
    }
}

// ---------------- iou GEMM (bf16 mma.sync, 2-term split) ----------------
// CTA = 128 same-type nodes. D = hsum @ U_iou[t] + b_iou, N=384 in 3 chunks.
__global__ __launch_bounds__(256) void k_iou(
    const float* __restrict__ U_iou, const float* __restrict__ b_iou,
    float* __restrict__ out)
{
    extern __shared__ __align__(1024) char smem[];
    const uint32_t sb = smem_u32(smem);
    const int tid = threadIdx.x, wid = tid >> 5, lane = tid & 31;

    int t, rowstart, cnt;
    if (!find_chunk(blockIdx.x, NTI, t, rowstart, cnt)) return;

    int* sh_node = (int*)smem;
    float* bst = (float*)(smem + I_BIAS);
    if (tid < 128) sh_node[tid] = g_sorted[rowstart + min(tid, cnt - 1)];
    __syncthreads();

    // ---- A loader: resident hi/lo tiles for full K (2 halves of 64) ----
#pragma unroll 4
    for (int i = 0; i < 32; i++) {
        int task = tid + 256 * i;
        int jl2 = task & 63, n = task >> 6;
        float2 v = *(const float2*)&g_hsum[(size_t)sh_node[n] * HH + 2 * jl2];
        int half = jl2 >> 5, jj = jl2 & 31;
        uint32_t hi, lo;
        split_bf(v.x, v.y, hi, lo);
        uint32_t off = half * 16384 + SW128((uint32_t)(n * 128 + jj * 4));
        *(uint32_t*)(smem + I_AHI + off) = hi;
        *(uint32_t*)(smem + I_ALO + off) = lo;
    }

    const int mbase = wid * 16;
    const uint32_t offA0 = (uint32_t)((mbase + (lane & 15)) * 128 + ((lane >> 4) << 4));
    const uint32_t swA = (offA0 >> 3) & 0x70;
    const uint32_t offB0 = (uint32_t)(((lane & 7) + ((lane >> 4) << 3)) * 128 + ((lane & 8) * 2));
    const uint32_t swB = (offB0 >> 3) & 0x70;

    for (int nc = 0; nc < 3; nc++) {
        __syncthreads();   // prior epilogue done before bias/B overwrite
        if (tid < 128) bst[tid] = b_iou[t * 384 + nc * 128 + tid];

        float acc[16][4];
#pragma unroll
        for (int i = 0; i < 16; i++)
#pragma unroll
            for (int j = 0; j < 4; j++) acc[i][j] = 0.f;

        for (int kc = 0; kc < 2; kc++) {
            // B loader: Bt[col][jl] = U_iou[t][kc*64+jl][nc*128+col]
#pragma unroll 4
            for (int i = 0; i < 16; i++) {
                int jl2 = i * 2 + (tid >> 7);
                int col = tid & 127;
                const float* Up = U_iou + (size_t)t * HH * 384 + (size_t)(kc * 64 + 2 * jl2) * 384 + nc * 128 + col;
                float v0 = Up[0];
                float v1 = Up[384];
                uint32_t hi, lo;
                split_bf(v0, v1, hi, lo);
                uint32_t off = SW128((uint32_t)(col * 128 + jl2 * 4));
                *(uint32_t*)(smem + I_BHI + off) = hi;
                *(uint32_t*)(smem + I_BLO + off) = lo;
            }
            __syncthreads();
            uint32_t AhiB = sb + I_AHI + kc * 16384;
            uint32_t AloB = sb + I_ALO + kc * 16384;
#pragma unroll
            for (int pass = 0; pass < 3; pass++) {
                uint32_t Ab = (pass == 2) ? AloB : AhiB;
                uint32_t Bb = sb + ((pass == 1) ? I_BLO : I_BHI);
#pragma unroll
                for (int ks = 0; ks < 4; ks++) {
                    uint32_t af[4];
                    ldsm_x4(af, Ab + ((offA0 + ks * 32) ^ swA));
#pragma unroll
                    for (int nt2 = 0; nt2 < 8; nt2++) {
                        uint32_t bfr[4];
                        ldsm_x4(bfr, Bb + nt2 * 2048 + ((offB0 + ks * 32) ^ swB));
                        mma16816(acc[2 * nt2], af, bfr);
                        mma16816(acc[2 * nt2 + 1], af, bfr + 2);
                    }
                }
            }
            __syncthreads();   // mma done before next B overwrite
        }

        // ---- epilogue: bias + store (32B-sector float2 stores) ----
        const int row0 = mbase + (lane >> 2), row1 = row0 + 8;
        const int q = lane & 3;
#pragma unroll
        for (int nt = 0; nt < 16; nt++) {
            int cl = nt * 8 + 2 * q;
            float2 b2 = *(float2*)&bst[cl];
            if (row0 < cnt)
                *(float2*)&out[(size_t)sh_node[row0] * 512 + nc * 128 + cl] =
                    make_float2(acc[nt][0] + b2.x, acc[nt][1] + b2.y);
            if (row1 < cnt)
                *(float2*)&out[(size_t)sh_node[row1] * 512 + nc * 128 + cl] =
                    make_float2(acc[nt][2] + b2.x, acc[nt][3] + b2.y);
        }
    }
}

// ---------------- launch ----------------
extern "C" void kernel_launch(void* const* d_in, const int* in_sizes, int n_in,
                              void* d_out, int out_size) {
    const float* h       = (const float*)d_in[0];
    const float* c       = (const float*)d_in[1];
    const float* f_input = (const float*)d_in[2];
    const int*   type_id = (const int*)d_in[3];
    const float* U_iou   = (const float*)d_in[4];
    const float* b_iou   = (const float*)d_in[5];
    const float* U_f     = (const float*)d_in[6];
    const float* b_f     = (const float*)d_in[7];
    float* out = (float*)d_out;

    static int attr_done = 0;
    if (!attr_done) {
        cudaFuncSetAttribute(k_forget, cudaFuncAttributeMaxDynamicSharedMemorySize, F_SMEM);
        cudaFuncSetAttribute(k_iou, cudaFuncAttributeMaxDynamicSharedMemorySize, I_SMEM);
        attr_done = 1;
    }

    k_zero<<<1, 32>>>();
    k_hist<<<NN / 256, 256>>>(type_id);
    k_scan<<<1, 1>>>();
    k_scatter<<<NN / 256, 256>>>(type_id);
    k_forget<<<GRID_F, 256, F_SMEM>>>(h, c, f_input, U_f, b_f, out);
    k_iou<<<GRID_I, 256, I_SMEM>>>(U_iou, b_iou, out);
}

// round 5
// speedup vs baseline: 2.1660x; 1.6512x over previous
#include <cuda_runtime.h>
#include <math.h>
#include <cstdint>

// Problem constants.
#define NN 65536
#define KK 8
#define HH 128
#define TT 4

#define NTF 16
#define GRID_F (NN / NTF + TT)
#define NTI 128
#define GRID_I (NN / NTI + TT)

// ---- forget kernel smem map (bytes). A/B rows padded to 68 f32 (conflict-free). ----
#define F_FI   64
#define F_A    8320
#define F_B    (F_A + 34816)
#define F_SMEM (F_B + 34816)      // 77952

// ---- iou kernel smem map. A rows padded to 132 f32, B to 68. ----
#define I_BIAS 512
#define I_A    2048
#define I_B    (I_A + 67584)
#define I_SMEM (I_B + 34816)      // 104448

// ---------------- device scratch ----------------
__device__ int g_base[TT + 1];
__device__ int g_cursor[TT];
__device__ int g_sorted[NN];
__device__ float g_hsum[NN * HH];

// ---------------- helpers ----------------
__device__ __forceinline__ uint32_t smem_u32(const void* p) {
    uint32_t a;
    asm("{ .reg .u64 t; cvta.to.shared.u64 t, %1; cvt.u32.u64 %0, t; }" : "=r"(a) : "l"(p));
    return a;
}
__device__ __forceinline__ float tf32r(float x) {
    float r; asm("cvt.rna.tf32.f32 %0, %1;" : "=f"(r) : "f"(x)); return r;
}
__device__ __forceinline__ void ldsm4(uint32_t* r, uint32_t a) {
    asm volatile("ldmatrix.sync.aligned.m8n8.x4.shared.b16 {%0,%1,%2,%3}, [%4];"
        : "=r"(r[0]), "=r"(r[1]), "=r"(r[2]), "=r"(r[3]) : "r"(a));
}
__device__ __forceinline__ void mma8(float* d, const uint32_t* a, uint32_t b0, uint32_t b1) {
    asm volatile("mma.sync.aligned.m16n8k8.row.col.f32.tf32.tf32.f32 "
        "{%0,%1,%2,%3}, {%4,%5,%6,%7}, {%8,%9}, {%0,%1,%2,%3};"
        : "+f"(d[0]), "+f"(d[1]), "+f"(d[2]), "+f"(d[3])
        : "r"(a[0]), "r"(a[1]), "r"(a[2]), "r"(a[3]), "r"(b0), "r"(b1));
}
__device__ __forceinline__ float sigm(float x) { return 1.f / (1.f + __expf(-x)); }

__device__ __forceinline__ bool find_chunk(int b, int NT, int& t, int& rowstart, int& cnt) {
    int cb = 0;
#pragma unroll
    for (int tt = 0; tt < TT; tt++) {
        int lo = g_base[tt], hi = g_base[tt + 1];
        int ch = (hi - lo + NT - 1) / NT;
        if (b >= cb && b < cb + ch) {
            t = tt;
            rowstart = lo + (b - cb) * NT;
            cnt = min(NT, hi - rowstart);
            return true;
        }
        cb += ch;
    }
    return false;
}

// ---------------- partition: histogram + scan in one CTA ----------------
__global__ __launch_bounds__(1024) void k_part1(const int* __restrict__ type_id) {
    __shared__ int sc[TT];
    int tid = threadIdx.x;
    if (tid < TT) sc[tid] = 0;
    __syncthreads();
    int c0 = 0, c1 = 0, c2 = 0, c3 = 0;
    const int4* p = (const int4*)type_id;
    for (int i = tid; i < NN / 4; i += 1024) {
        int4 v = p[i];
        c0 += (v.x == 0) + (v.y == 0) + (v.z == 0) + (v.w == 0);
        c1 += (v.x == 1) + (v.y == 1) + (v.z == 1) + (v.w == 1);
        c2 += (v.x == 2) + (v.y == 2) + (v.z == 2) + (v.w == 2);
        c3 += (v.x == 3) + (v.y == 3) + (v.z == 3) + (v.w == 3);
    }
#pragma unroll
    for (int d = 16; d; d >>= 1) {
        c0 += __shfl_xor_sync(0xffffffffu, c0, d);
        c1 += __shfl_xor_sync(0xffffffffu, c1, d);
        c2 += __shfl_xor_sync(0xffffffffu, c2, d);
        c3 += __shfl_xor_sync(0xffffffffu, c3, d);
    }
    if ((tid & 31) == 0) {
        atomicAdd(&sc[0], c0); atomicAdd(&sc[1], c1);
        atomicAdd(&sc[2], c2); atomicAdd(&sc[3], c3);
    }
    __syncthreads();
    if (tid == 0) {
        int b = 0;
#pragma unroll
        for (int t = 0; t < TT; t++) { g_base[t] = b; g_cursor[t] = b; b += sc[t]; }
        g_base[TT] = b;
    }
}

__global__ void k_scatter(const int* __restrict__ type_id) {
    __shared__ int w_off[8][TT];
    __shared__ int blk_base[TT];
    int n = blockIdx.x * 256 + threadIdx.x;
    int t = type_id[n];
    int w = threadIdx.x >> 5, lane = threadIdx.x & 31;
    int rank = 0;
#pragma unroll
    for (int tt = 0; tt < TT; tt++) {
        unsigned bm = __ballot_sync(0xffffffffu, t == tt);
        if (lane == 0) w_off[w][tt] = __popc(bm);
        if (t == tt) rank = __popc(bm & ((1u << lane) - 1));
    }
    __syncthreads();
    if (threadIdx.x < TT) {
        int tt = threadIdx.x, s = 0;
#pragma unroll
        for (int ww = 0; ww < 8; ww++) { int v = w_off[ww][tt]; w_off[ww][tt] = s; s += v; }
        blk_base[tt] = atomicAdd(&g_cursor[tt], s);
    }
    __syncthreads();
    g_sorted[blk_base[t] + w_off[w][t] + rank] = n;
}

// ---------------- forget-gate GEMM (tf32 1-pass) ----------------
// CTA = 16 same-type nodes -> M=128 rows, N=128, K=128 in 2 chunks of 64.
// Side product g_hsum; fused sigmoid*c child-reduction epilogue.
__global__ __launch_bounds__(256) void k_forget(
    const float* __restrict__ h, const float* __restrict__ c,
    const float* __restrict__ f_input, const float* __restrict__ U_f,
    const float* __restrict__ b_f, float* __restrict__ out)
{
    extern __shared__ __align__(1024) char smem[];
    const uint32_t sb = smem_u32(smem);
    const int tid = threadIdx.x, wid = tid >> 5, lane = tid & 31;

    int t, rowstart, cnt;
    if (!find_chunk(blockIdx.x, NTF, t, rowstart, cnt)) return;

    int* sh_node = (int*)smem;
    float* fi = (float*)(smem + F_FI);
    if (tid < NTF) sh_node[tid] = g_sorted[rowstart + min(tid, cnt - 1)];
    __syncthreads();

    // fi stage: f_input + b_f (16 x 128)
#pragma unroll
    for (int i = 0; i < 8; i++) {
        int idx = tid + 256 * i;
        int n = idx >> 7, col = idx & 127;
        fi[idx] = f_input[(size_t)sh_node[n] * HH + col] + b_f[t * HH + col];
    }

    float acc[16][4];
#pragma unroll
    for (int i = 0; i < 16; i++)
#pragma unroll
        for (int j = 0; j < 4; j++) acc[i][j] = 0.f;

    const int m0 = wid * 16;
    const uint32_t aaddr = sb + F_A +
        (((m0 + (lane & 7) + ((lane >> 3) & 1) * 8) * 68 + (lane >> 4) * 4) << 2);
    const uint32_t baddr = sb + F_B +
        ((((lane & 7) + (lane >> 4) * 8) * 68 + ((lane >> 3) & 1) * 4) << 2);

    for (int kc = 0; kc < 2; kc++) {
        if (kc > 0) __syncthreads();
        // A loader: [128 m][64 k] tf32, row stride 68
#pragma unroll
        for (int i = 0; i < 8; i++) {
            int task = tid + 256 * i;
            int m = task >> 4, kq = task & 15;
            int nd = sh_node[m >> 3];
            float4 v = *(const float4*)&h[((size_t)nd * KK + (m & 7)) * HH + kc * 64 + kq * 4];
            *(float4*)(smem + F_A + (m * 68 + kq * 4) * 4) =
                make_float4(tf32r(v.x), tf32r(v.y), tf32r(v.z), tf32r(v.w));
        }
        // B loader: Bt[col][j] from U_f[t][j][col]
#pragma unroll
        for (int i = 0; i < 8; i++) {
            int task = tid + 256 * i;
            int col = task & 127, jq = task >> 7;
            const float* Up = U_f + (size_t)t * HH * HH + (kc * 64 + jq * 4) * HH + col;
            *(float4*)(smem + F_B + (col * 68 + jq * 4) * 4) =
                make_float4(tf32r(Up[0]), tf32r(Up[128]), tf32r(Up[256]), tf32r(Up[384]));
        }
        __syncthreads();
        // child-sum side product from staged A
#pragma unroll
        for (int i = 0; i < 4; i++) {
            int task = tid + 256 * i;
            int n = task >> 6, j = task & 63;
            float s = 0.f;
#pragma unroll
            for (int ch = 0; ch < KK; ch++)
                s += *(const float*)(smem + F_A + ((n * 8 + ch) * 68 + j) * 4);
            g_hsum[(size_t)sh_node[n] * HH + kc * 64 + j] = s;
        }
        // mma: 8 k-steps x 16 n-tiles
#pragma unroll
        for (int ks = 0; ks < 8; ks++) {
            uint32_t af[4];
            ldsm4(af, aaddr + ks * 32);
#pragma unroll
            for (int nb = 0; nb < 8; nb++) {
                uint32_t bf[4];
                ldsm4(bf, baddr + nb * 4352 + ks * 32);
                mma8(acc[2 * nb], af, bf[0], bf[1]);
                mma8(acc[2 * nb + 1], af, bf[2], bf[3]);
            }
        }
    }

    // ---- epilogue: sigmoid * c, reduce 8 children, store ----
    const int node0 = wid * 2, node1 = node0 + 1;
    const int child = lane >> 2, q = lane & 3;
    const int nd0 = sh_node[node0], nd1 = sh_node[node1];
    const float* c0p = c + ((size_t)nd0 * KK + child) * HH;
    const float* c1p = c + ((size_t)nd1 * KK + child) * HH;
#pragma unroll
    for (int nt = 0; nt < 16; nt++) {
        int col = nt * 8 + 2 * q;
        float2 f0 = *(float2*)&fi[node0 * 128 + col];
        float2 f1 = *(float2*)&fi[node1 * 128 + col];
        float2 cv0 = *(const float2*)(c0p + col);
        float2 cv1 = *(const float2*)(c1p + col);
        float v00 = sigm(acc[nt][0] + f0.x) * cv0.x;
        float v01 = sigm(acc[nt][1] + f0.y) * cv0.y;
        float v10 = sigm(acc[nt][2] + f1.x) * cv1.x;
        float v11 = sigm(acc[nt][3] + f1.y) * cv1.y;
#pragma unroll
        for (int d = 4; d < 32; d <<= 1) {
            v00 += __shfl_xor_sync(0xffffffffu, v00, d);
            v01 += __shfl_xor_sync(0xffffffffu, v01, d);
            v10 += __shfl_xor_sync(0xffffffffu, v10, d);
            v11 += __shfl_xor_sync(0xffffffffu, v11, d);
        }
        if (lane < 4 && node0 < cnt)
            *(float2*)&out[(size_t)nd0 * 512 + 384 + nt * 8 + 2 * lane] = make_float2(v00, v01);
        if (lane >= 4 && lane < 8 && node1 < cnt)
            *(float2*)&out[(size_t)nd1 * 512 + 384 + nt * 8 + 2 * (lane - 4)] = make_float2(v10, v11);
    }
}

// ---------------- iou GEMM (tf32 1-pass) ----------------
// CTA = 128 same-type nodes. D = hsum @ U_iou[t] + b_iou. N=384 in 3 chunks.
__global__ __launch_bounds__(256) void k_iou(
    const float* __restrict__ U_iou, const float* __restrict__ b_iou,
    float* __restrict__ out)
{
    extern __shared__ __align__(1024) char smem[];
    const uint32_t sb = smem_u32(smem);
    const int tid = threadIdx.x, wid = tid >> 5, lane = tid & 31;

    int t, rowstart, cnt;
    if (!find_chunk(blockIdx.x, NTI, t, rowstart, cnt)) return;

    int* sh_node = (int*)smem;
    float* bst = (float*)(smem + I_BIAS);
    if (tid < 128) {
        sh_node[tid] = g_sorted[rowstart + min(tid, cnt - 1)];
        bst[tid] = b_iou[t * 384 + tid];
        bst[tid + 128] = b_iou[t * 384 + 128 + tid];
        bst[tid + 256] = b_iou[t * 384 + 256 + tid];
    }
    __syncthreads();

    // A loader: [128 m][128 k] tf32, row stride 132 (full K resident)
#pragma unroll
    for (int i = 0; i < 16; i++) {
        int task = tid + 256 * i;
        int m = task >> 5, kq = task & 31;
        float4 v = *(const float4*)&g_hsum[(size_t)sh_node[m] * HH + kq * 4];
        *(float4*)(smem + I_A + (m * 132 + kq * 4) * 4) =
            make_float4(tf32r(v.x), tf32r(v.y), tf32r(v.z), tf32r(v.w));
    }

    const int m0 = wid * 16;
    const uint32_t aaddr = sb + I_A +
        (((m0 + (lane & 7) + ((lane >> 3) & 1) * 8) * 132 + (lane >> 4) * 4) << 2);
    const uint32_t baddr = sb + I_B +
        ((((lane & 7) + (lane >> 4) * 8) * 68 + ((lane >> 3) & 1) * 4) << 2);

    for (int nc = 0; nc < 3; nc++) {
        float acc[16][4];
#pragma unroll
        for (int i = 0; i < 16; i++)
#pragma unroll
            for (int j = 0; j < 4; j++) acc[i][j] = 0.f;

        for (int kc = 0; kc < 2; kc++) {
            __syncthreads();   // A ready (first) / previous mma done before B overwrite
            // B loader: Bt[col][j] from U_iou[t][j][nc*128+col]
#pragma unroll
            for (int i = 0; i < 8; i++) {
                int task = tid + 256 * i;
                int col = task & 127, jq = task >> 7;
                const float* Up = U_iou + (size_t)t * HH * 384 +
                                  (size_t)(kc * 64 + jq * 4) * 384 + nc * 128 + col;
                *(float4*)(smem + I_B + (col * 68 + jq * 4) * 4) =
                    make_float4(tf32r(Up[0]), tf32r(Up[384]), tf32r(Up[768]), tf32r(Up[1152]));
            }
            __syncthreads();
#pragma unroll
            for (int ks = 0; ks < 8; ks++) {
                uint32_t af[4];
                ldsm4(af, aaddr + kc * 256 + ks * 32);
#pragma unroll
                for (int nb = 0; nb < 8; nb++) {
                    uint32_t bf[4];
                    ldsm4(bf, baddr + nb * 4352 + ks * 32);
                    mma8(acc[2 * nb], af, bf[0], bf[1]);
                    mma8(acc[2 * nb + 1], af, bf[2], bf[3]);
                }
            }
        }

        // epilogue: bias + float2 stores
        const int row0 = m0 + (lane >> 2), row1 = row0 + 8;
        const int q = lane & 3;
#pragma unroll
        for (int nt = 0; nt < 16; nt++) {
            int cl = nt * 8 + 2 * q;
            float2 b2 = *(float2*)&bst[nc * 128 + cl];
            if (row0 < cnt)
                *(float2*)&out[(size_t)sh_node[row0] * 512 + nc * 128 + cl] =
                    make_float2(acc[nt][0] + b2.x, acc[nt][1] + b2.y);
            if (row1 < cnt)
                *(float2*)&out[(size_t)sh_node[row1] * 512 + nc * 128 + cl] =
                    make_float2(acc[nt][2] + b2.x, acc[nt][3] + b2.y);
        }
    }
}

// ---------------- launch ----------------
extern "C" void kernel_launch(void* const* d_in, const int* in_sizes, int n_in,
                              void* d_out, int out_size) {
    const float* h       = (const float*)d_in[0];
    const float* c       = (const float*)d_in[1];
    const float* f_input = (const float*)d_in[2];
    const int*   type_id = (const int*)d_in[3];
    const float* U_iou   = (const float*)d_in[4];
    const float* b_iou   = (const float*)d_in[5];
    const float* U_f     = (const float*)d_in[6];
    const float* b_f     = (const float*)d_in[7];
    float* out = (float*)d_out;

    static int attr_done = 0;
    if (!attr_done) {
        cudaFuncSetAttribute(k_forget, cudaFuncAttributeMaxDynamicSharedMemorySize, F_SMEM);
        cudaFuncSetAttribute(k_iou, cudaFuncAttributeMaxDynamicSharedMemorySize, I_SMEM);
        attr_done = 1;
    }

    k_part1<<<1, 1024>>>(type_id);
    k_scatter<<<NN / 256, 256>>>(type_id);
    k_forget<<<GRID_F, 256, F_SMEM>>>(h, c, f_input, U_f, b_f, out);
    k_iou<<<GRID_I, 256, I_SMEM>>>(U_iou, b_iou, out);
}

// round 7
// speedup vs baseline: 3.2834x; 1.5159x over previous
#include <cuda_runtime.h>
#include <cuda_fp16.h>
#include <math.h>
#include <cstdint>

// Problem constants.
#define NN 65536
#define KK 8
#define HH 128
#define TT 4

#define NTF 16
#define GRID_F (NN / NTF + TT)
#define NTI 128
#define GRID_I (NN / NTI + TT)

// fp16 tile rows: 128 k-halves padded to 136 (272 bytes, bank-stride 4 -> conflict-free).
#define ROWB 272

// ---- forget kernel smem map (bytes) ----
#define F_FI   64
#define F_A    8320
#define F_B    (F_A + 34816)
#define F_SMEM (F_B + 34816)      // 77952 -> 2 CTAs/SM

// ---- iou kernel smem map ----
#define I_BST  512
#define I_A    2048
#define I_B    (I_A + 34816)
#define I_SMEM (I_B + 34816)      // 71680 -> 2 CTAs/SM

// ---------------- device scratch ----------------
__device__ int g_base[TT + 1];
__device__ int g_cursor[TT];
__device__ int g_sorted[NN];
__device__ float g_hsum[NN * HH];

// ---------------- helpers ----------------
__device__ __forceinline__ uint32_t smem_u32(const void* p) {
    uint32_t a;
    asm("{ .reg .u64 t; cvta.to.shared.u64 t, %1; cvt.u32.u64 %0, t; }" : "=r"(a) : "l"(p));
    return a;
}
__device__ __forceinline__ uint32_t h2u(float x, float y) {
    __half2 h = __floats2half2_rn(x, y);
    return *reinterpret_cast<uint32_t*>(&h);
}
__device__ __forceinline__ void ldsm4(uint32_t* r, uint32_t a) {
    asm volatile("ldmatrix.sync.aligned.m8n8.x4.shared.b16 {%0,%1,%2,%3}, [%4];"
        : "=r"(r[0]), "=r"(r[1]), "=r"(r[2]), "=r"(r[3]) : "r"(a));
}
__device__ __forceinline__ void mma16(float* d, const uint32_t* a, uint32_t b0, uint32_t b1) {
    asm volatile("mma.sync.aligned.m16n8k16.row.col.f32.f16.f16.f32 "
        "{%0,%1,%2,%3}, {%4,%5,%6,%7}, {%8,%9}, {%0,%1,%2,%3};"
        : "+f"(d[0]), "+f"(d[1]), "+f"(d[2]), "+f"(d[3])
        : "r"(a[0]), "r"(a[1]), "r"(a[2]), "r"(a[3]), "r"(b0), "r"(b1));
}
__device__ __forceinline__ float sigm(float x) { return 1.f / (1.f + __expf(-x)); }

__device__ __forceinline__ bool find_chunk(int b, int NT, int& t, int& rowstart, int& cnt) {
    int cb = 0;
#pragma unroll
    for (int tt = 0; tt < TT; tt++) {
        int lo = g_base[tt], hi = g_base[tt + 1];
        int ch = (hi - lo + NT - 1) / NT;
        if (b >= cb && b < cb + ch) {
            t = tt;
            rowstart = lo + (b - cb) * NT;
            cnt = min(NT, hi - rowstart);
            return true;
        }
        cb += ch;
    }
    return false;
}

// ---------------- partition: histogram + scan in one CTA ----------------
__global__ __launch_bounds__(1024) void k_part1(const int* __restrict__ type_id) {
    __shared__ int sc[TT];
    int tid = threadIdx.x;
    if (tid < TT) sc[tid] = 0;
    __syncthreads();
    int c0 = 0, c1 = 0, c2 = 0, c3 = 0;
    const int4* p = (const int4*)type_id;
    for (int i = tid; i < NN / 4; i += 1024) {
        int4 v = p[i];
        c0 += (v.x == 0) + (v.y == 0) + (v.z == 0) + (v.w == 0);
        c1 += (v.x == 1) + (v.y == 1) + (v.z == 1) + (v.w == 1);
        c2 += (v.x == 2) + (v.y == 2) + (v.z == 2) + (v.w == 2);
        c3 += (v.x == 3) + (v.y == 3) + (v.z == 3) + (v.w == 3);
    }
#pragma unroll
    for (int d = 16; d; d >>= 1) {
        c0 += __shfl_xor_sync(0xffffffffu, c0, d);
        c1 += __shfl_xor_sync(0xffffffffu, c1, d);
        c2 += __shfl_xor_sync(0xffffffffu, c2, d);
        c3 += __shfl_xor_sync(0xffffffffu, c3, d);
    }
    if ((tid & 31) == 0) {
        atomicAdd(&sc[0], c0); atomicAdd(&sc[1], c1);
        atomicAdd(&sc[2], c2); atomicAdd(&sc[3], c3);
    }
    __syncthreads();
    if (tid == 0) {
        int b = 0;
#pragma unroll
        for (int t = 0; t < TT; t++) { g_base[t] = b; g_cursor[t] = b; b += sc[t]; }
        g_base[TT] = b;
    }
}

__global__ void k_scatter(const int* __restrict__ type_id) {
    __shared__ int w_off[8][TT];
    __shared__ int blk_base[TT];
    int n = blockIdx.x * 256 + threadIdx.x;
    int t = type_id[n];
    int w = threadIdx.x >> 5, lane = threadIdx.x & 31;
    int rank = 0;
#pragma unroll
    for (int tt = 0; tt < TT; tt++) {
        unsigned bm = __ballot_sync(0xffffffffu, t == tt);
        if (lane == 0) w_off[w][tt] = __popc(bm);
        if (t == tt) rank = __popc(bm & ((1u << lane) - 1));
    }
    __syncthreads();
    if (threadIdx.x < TT) {
        int tt = threadIdx.x, s = 0;
#pragma unroll
        for (int ww = 0; ww < 8; ww++) { int v = w_off[ww][tt]; w_off[ww][tt] = s; s += v; }
        blk_base[tt] = atomicAdd(&g_cursor[tt], s);
    }
    __syncthreads();
    g_sorted[blk_base[t] + w_off[w][t] + rank] = n;
}

// ---------------- forget-gate GEMM (fp16 1-pass, K fully resident) ----------------
// CTA = 16 same-type nodes -> M=128 rows, N=128, K=128. One load phase, one sync, one mma block.
// hsum computed from original f32 h during the A load. Fused sigmoid*c child-reduce epilogue.
__global__ __launch_bounds__(256, 2) void k_forget(
    const float* __restrict__ h, const float* __restrict__ c,
    const float* __restrict__ f_input, const float* __restrict__ U_f,
    const float* __restrict__ b_f, float* __restrict__ out)
{
    extern __shared__ __align__(1024) char smem[];
    const uint32_t sb = smem_u32(smem);
    const int tid = threadIdx.x, wid = tid >> 5, lane = tid & 31;

    int t, rowstart, cnt;
    if (!find_chunk(blockIdx.x, NTF, t, rowstart, cnt)) return;

    int* sh_node = (int*)smem;
    float* fi = (float*)(smem + F_FI);
    if (tid < NTF) sh_node[tid] = g_sorted[rowstart + min(tid, cnt - 1)];
    __syncthreads();

    // fi stage: f_input + b_f (16 x 128)
#pragma unroll
    for (int i = 0; i < 8; i++) {
        int idx = tid + 256 * i;
        int n = idx >> 7, col = idx & 127;
        fi[idx] = f_input[(size_t)sh_node[n] * HH + col] + b_f[t * HH + col];
    }

    // A loader + f32 hsum: task (node, j4), thread covers all 8 children.
#pragma unroll
    for (int i = 0; i < 2; i++) {
        int task = tid + 256 * i;
        int j4 = task & 31, n = task >> 5;
        int nd = sh_node[n];
        float4 s = make_float4(0.f, 0.f, 0.f, 0.f);
#pragma unroll
        for (int ch = 0; ch < KK; ch++) {
            float4 v = *(const float4*)&h[((size_t)nd * KK + ch) * HH + j4 * 4];
            s.x += v.x; s.y += v.y; s.z += v.z; s.w += v.w;
            uint2 w = make_uint2(h2u(v.x, v.y), h2u(v.z, v.w));
            *(uint2*)(smem + F_A + (n * KK + ch) * ROWB + j4 * 8) = w;
        }
        *(float4*)&g_hsum[(size_t)nd * HH + j4 * 4] = s;
    }

    // B loader: Bt[col][k] from U_f[t][k][col], 8 k per task.
#pragma unroll
    for (int i = 0; i < 8; i++) {
        int task = tid + 256 * i;
        int col = task & 127, j8 = task >> 7;   // j8 in 0..15
        const float* Up = U_f + (size_t)t * HH * HH + (size_t)j8 * 8 * HH + col;
        float v0 = Up[0], v1 = Up[128], v2 = Up[256], v3 = Up[384];
        float v4 = Up[512], v5 = Up[640], v6 = Up[768], v7 = Up[896];
        uint4 w = make_uint4(h2u(v0, v1), h2u(v2, v3), h2u(v4, v5), h2u(v6, v7));
        *(uint4*)(smem + F_B + col * ROWB + j8 * 16) = w;
    }
    __syncthreads();

    // mma: 8 k-steps of k16, n128 in 8 n16-groups.
    float acc[16][4];
#pragma unroll
    for (int i = 0; i < 16; i++)
#pragma unroll
        for (int j = 0; j < 4; j++) acc[i][j] = 0.f;

    const int m0 = wid * 16;
    const uint32_t aaddr = sb + F_A + (m0 + (lane & 15)) * ROWB + ((lane >> 4) << 4);
    const uint32_t baddr = sb + F_B + ((lane & 7) + (lane >> 4) * 8) * ROWB + (lane & 8) * 2;

#pragma unroll
    for (int ks = 0; ks < 8; ks++) {
        uint32_t af[4];
        ldsm4(af, aaddr + ks * 32);
#pragma unroll
        for (int nb = 0; nb < 8; nb++) {
            uint32_t bf[4];
            ldsm4(bf, baddr + nb * 16 * ROWB + ks * 32);
            mma16(acc[2 * nb], af, bf[0], bf[1]);
            mma16(acc[2 * nb + 1], af, bf[2], bf[3]);
        }
    }

    // ---- epilogue: sigmoid * c, reduce 8 children, store ----
    const int node0 = wid * 2, node1 = node0 + 1;
    const int child = lane >> 2, q = lane & 3;
    const int nd0 = sh_node[node0], nd1 = sh_node[node1];
    const float* c0p = c + ((size_t)nd0 * KK + child) * HH;
    const float* c1p = c + ((size_t)nd1 * KK + child) * HH;
#pragma unroll
    for (int nt = 0; nt < 16; nt++) {
        int col = nt * 8 + 2 * q;
        float2 f0 = *(float2*)&fi[node0 * 128 + col];
        float2 f1 = *(float2*)&fi[node1 * 128 + col];
        float2 cv0 = *(const float2*)(c0p + col);
        float2 cv1 = *(const float2*)(c1p + col);
        float v00 = sigm(acc[nt][0] + f0.x) * cv0.x;
        float v01 = sigm(acc[nt][1] + f0.y) * cv0.y;
        float v10 = sigm(acc[nt][2] + f1.x) * cv1.x;
        float v11 = sigm(acc[nt][3] + f1.y) * cv1.y;
#pragma unroll
        for (int d = 4; d < 32; d <<= 1) {
            v00 += __shfl_xor_sync(0xffffffffu, v00, d);
            v01 += __shfl_xor_sync(0xffffffffu, v01, d);
            v10 += __shfl_xor_sync(0xffffffffu, v10, d);
            v11 += __shfl_xor_sync(0xffffffffu, v11, d);
        }
        if (lane < 4 && node0 < cnt)
            *(float2*)&out[(size_t)nd0 * 512 + 384 + nt * 8 + 2 * lane] = make_float2(v00, v01);
        if (lane >= 4 && lane < 8 && node1 < cnt)
            *(float2*)&out[(size_t)nd1 * 512 + 384 + nt * 8 + 2 * (lane - 4)] = make_float2(v10, v11);
    }
}

// ---------------- iou GEMM (fp16 1-pass) ----------------
// CTA = 128 same-type nodes. D = hsum @ U_iou[t] + b_iou. A K-resident; 3 N-chunks.
__global__ __launch_bounds__(256, 2) void k_iou(
    const float* __restrict__ U_iou, const float* __restrict__ b_iou,
    float* __restrict__ out)
{
    extern __shared__ __align__(1024) char smem[];
    const uint32_t sb = smem_u32(smem);
    const int tid = threadIdx.x, wid = tid >> 5, lane = tid & 31;

    int t, rowstart, cnt;
    if (!find_chunk(blockIdx.x, NTI, t, rowstart, cnt)) return;

    int* sh_node = (int*)smem;
    float* bst = (float*)(smem + I_BST);
    if (tid < 128) {
        sh_node[tid] = g_sorted[rowstart + min(tid, cnt - 1)];
        bst[tid] = b_iou[t * 384 + tid];
        bst[tid + 128] = b_iou[t * 384 + 128 + tid];
        bst[tid + 256] = b_iou[t * 384 + 256 + tid];
    }
    __syncthreads();

    // A loader: [128 m][128 k] fp16
#pragma unroll
    for (int i = 0; i < 16; i++) {
        int task = tid + 256 * i;
        int m = task >> 5, j4 = task & 31;
        float4 v = *(const float4*)&g_hsum[(size_t)sh_node[m] * HH + j4 * 4];
        uint2 w = make_uint2(h2u(v.x, v.y), h2u(v.z, v.w));
        *(uint2*)(smem + I_A + m * ROWB + j4 * 8) = w;
    }

    const int m0 = wid * 16;
    const uint32_t aaddr = sb + I_A + (m0 + (lane & 15)) * ROWB + ((lane >> 4) << 4);
    const uint32_t baddr = sb + I_B + ((lane & 7) + (lane >> 4) * 8) * ROWB + (lane & 8) * 2;

    for (int nc = 0; nc < 3; nc++) {
        __syncthreads();   // A staged (first) / all warps done with previous B
        // B loader: Bt[col][k] from U_iou[t][k][nc*128+col]
#pragma unroll
        for (int i = 0; i < 8; i++) {
            int task = tid + 256 * i;
            int col = task & 127, j8 = task >> 7;
            const float* Up = U_iou + (size_t)t * HH * 384 + (size_t)j8 * 8 * 384 + nc * 128 + col;
            float v0 = Up[0],    v1 = Up[384],  v2 = Up[768],  v3 = Up[1152];
            float v4 = Up[1536], v5 = Up[1920], v6 = Up[2304], v7 = Up[2688];
            uint4 w = make_uint4(h2u(v0, v1), h2u(v2, v3), h2u(v4, v5), h2u(v6, v7));
            *(uint4*)(smem + I_B + col * ROWB + j8 * 16) = w;
        }
        __syncthreads();

        float acc[16][4];
#pragma unroll
        for (int i = 0; i < 16; i++)
#pragma unroll
            for (int j = 0; j < 4; j++) acc[i][j] = 0.f;

#pragma unroll
        for (int ks = 0; ks < 8; ks++) {
            uint32_t af[4];
            ldsm4(af, aaddr + ks * 32);
#pragma unroll
            for (int nb = 0; nb < 8; nb++) {
                uint32_t bf[4];
                ldsm4(bf, baddr + nb * 16 * ROWB + ks * 32);
                mma16(acc[2 * nb], af, bf[0], bf[1]);
                mma16(acc[2 * nb + 1], af, bf[2], bf[3]);
            }
        }

        // epilogue: bias + float2 stores
        const int row0 = m0 + (lane >> 2), row1 = row0 + 8;
        const int q = lane & 3;
#pragma unroll
        for (int nt = 0; nt < 16; nt++) {
            int cl = nt * 8 + 2 * q;
            float2 b2 = *(float2*)&bst[nc * 128 + cl];
            if (row0 < cnt)
                *(float2*)&out[(size_t)sh_node[row0] * 512 + nc * 128 + cl] =
                    make_float2(acc[nt][0] + b2.x, acc[nt][1] + b2.y);
            if (row1 < cnt)
                *(float2*)&out[(size_t)sh_node[row1] * 512 + nc * 128 + cl] =
                    make_float2(acc[nt][2] + b2.x, acc[nt][3] + b2.y);
        }
    }
}

// ---------------- launch ----------------
extern "C" void kernel_launch(void* const* d_in, const int* in_sizes, int n_in,
                              void* d_out, int out_size) {
    const float* h       = (const float*)d_in[0];
    const float* c       = (const float*)d_in[1];
    const float* f_input = (const float*)d_in[2];
    const int*   type_id = (const int*)d_in[3];
    const float* U_iou   = (const float*)d_in[4];
    const float* b_iou   = (const float*)d_in[5];
    const float* U_f     = (const float*)d_in[6];
    const float* b_f     = (const float*)d_in[7];
    float* out = (float*)d_out;

    static int attr_done = 0;
    if (!attr_done) {
        cudaFuncSetAttribute(k_forget, cudaFuncAttributeMaxDynamicSharedMemorySize, F_SMEM);
        cudaFuncSetAttribute(k_iou, cudaFuncAttributeMaxDynamicSharedMemorySize, I_SMEM);
        attr_done = 1;
    }

    k_part1<<<1, 1024>>>(type_id);
    k_scatter<<<NN / 256, 256>>>(type_id);
    k_forget<<<GRID_F, 256, F_SMEM>>>(h, c, f_input, U_f, b_f, out);
    k_iou<<<GRID_I, 256, I_SMEM>>>(U_iou, b_iou, out);
}